// round 16
// baseline (speedup 1.0000x reference)
#include <cuda_runtime.h>
#include <cuda_fp16.h>
#include <cstdint>

#define N_IMG 8
#define C_IN  256
#define C_OUT 256
#define H_DIM 64
#define W_DIM 64
#define HW    4096
#define GROUPS 32
#define EPS_GN 1e-5f
#define CK    (C_IN * 9)   // 2304
#define NT    36           // K-tiles of 64 ck' (single tap k, 64 channels each)

// ---- dynamic smem layout for k_deform (bytes) ----
#define SM_IDX   0                    // ushort4[576] = 4608
#define SM_WGT   4608                 // float4[576]  = 9216 -> 13824, pad 14336
#define SM_A     14336                // 2 bufs x 8192 = 16384 -> 30720
#define SM_B     30720                // 2 bufs x 32768 = 65536 -> 96256
#define SM_TOTAL 96256                // 94 KB -> 2 CTAs/SM
#define SM_OUT   SM_A                 // epilogue staging (69632 <= 81920)
#define OSTR     68                   // f32 stride for out staging rows

static __device__ __forceinline__ uint32_t smem_u32(const void* p) {
    uint32_t a;
    asm("{ .reg .u64 t; cvta.to.shared.u64 t, %1; cvt.u32.u64 %0, t; }" : "=r"(a) : "l"(p));
    return a;
}
static __device__ __forceinline__ void lds32(uint32_t& d, uint32_t a) {
    asm volatile("ld.shared.b32 %0, [%1];" : "=r"(d) : "r"(a));
}
static __device__ __forceinline__ void ldmx4(uint32_t* r, uint32_t a) {
    asm volatile("ldmatrix.sync.aligned.m8n8.x4.shared.b16 {%0,%1,%2,%3}, [%4];"
                 : "=r"(r[0]), "=r"(r[1]), "=r"(r[2]), "=r"(r[3]) : "r"(a));
}
static __device__ __forceinline__ void mma16816(float* c, const uint32_t* a,
                                                uint32_t b0, uint32_t b1) {
    asm volatile("mma.sync.aligned.m16n8k16.row.col.f32.f16.f16.f32 "
                 "{%0,%1,%2,%3}, {%4,%5,%6,%7}, {%8,%9}, {%0,%1,%2,%3};"
                 : "+f"(c[0]), "+f"(c[1]), "+f"(c[2]), "+f"(c[3])
                 : "r"(a[0]), "r"(a[1]), "r"(a[2]), "r"(a[3]), "r"(b0), "r"(b1));
}
static __device__ __forceinline__ void cpasync16(uint32_t saddr, const void* g) {
    asm volatile("cp.async.cg.shared.global [%0], [%1], 16;" :: "r"(saddr), "l"(g) : "memory");
}
__device__ __forceinline__ unsigned long long pack2(float lo, float hi) {
    unsigned long long r;
    asm("mov.b64 %0, {%1, %2};" : "=l"(r) : "f"(lo), "f"(hi));
    return r;
}

// Scratch (static device globals; no runtime allocation)
__device__ float4 g_T[N_IMG * HW];                    // per-pixel 2x2 transform
__device__ __align__(16) __half g_wh[C_OUT * CK];     // weight fp16 [o][k*256+c]
__device__ __align__(16) __half g_xt[N_IMG * HW * C_IN]; // x fp16, [n][pix][c]
__device__ float2 g_stats[N_IMG * GROUPS];            // (mu, rsigma)

// ---------------------------------------------------------------------------
// Kernel 0a: w_dcn [o][c][k] -> fp16 g_wh [o][k*256+c]
// ---------------------------------------------------------------------------
__global__ void k_prep_w(const float* __restrict__ w) {
    int i = blockIdx.x * 256 + threadIdx.x;          // i = (o*256+c)*9 + k
    if (i >= C_OUT * CK) return;
    int k = i % 9;
    int oc = i / 9;
    int o = oc >> 8, c = oc & 255;
    g_wh[(size_t)o * CK + k * 256 + c] = __float2half_rn(w[i]);
}

// ---------------------------------------------------------------------------
// Kernel 0b: transpose x [n][c][pix] fp32 -> g_xt [n][pix][c] fp16 (tiled)
// ---------------------------------------------------------------------------
__global__ void __launch_bounds__(256) k_prep_x(const float* __restrict__ x) {
    __shared__ __half tile[32][33];
    int pt = blockIdx.x * 32;            // pixel tile
    int ct = blockIdx.y * 32;            // channel tile
    int n  = blockIdx.z;
    int tx = threadIdx.x, ty = threadIdx.y;   // (32, 8)
    const float* xb = x + ((size_t)n * C_IN + ct) * HW + pt;
#pragma unroll
    for (int i = ty; i < 32; i += 8)
        tile[i][tx] = __float2half_rn(xb[(size_t)i * HW + tx]);
    __syncthreads();
    __half* ob = g_xt + ((size_t)n * HW + pt) * C_IN + ct;
#pragma unroll
    for (int i = ty; i < 32; i += 8)
        ob[(size_t)i * C_IN + tx] = tile[tx][i];
}

// ---------------------------------------------------------------------------
// Kernel 1: tm = conv3x3(x, w_tm) + b_tm  -> T per pixel. Smem row-tiling:
// block = 4 rows; per channel, stage 6 zero-padded rows (stride 66) into a
// double-buffered tile; compute = 9 LDS + f32x2 FMAs (no scattered LDGs).
// ---------------------------------------------------------------------------
__global__ void __launch_bounds__(256) k_offsets(const float* __restrict__ x,
                                                 const float* __restrict__ w_tm,
                                                 const float* __restrict__ b_tm) {
    __shared__ unsigned long long ws01[CK];
    __shared__ unsigned long long ws23[CK];
    __shared__ float tile[2][6 * 66];
    int tid = threadIdx.x;
    for (int i = tid; i < CK; i += 256) {
        ws01[i] = pack2(w_tm[i],          w_tm[CK + i]);
        ws23[i] = pack2(w_tm[2 * CK + i], w_tm[3 * CK + i]);
    }
    for (int i = tid; i < 2 * 6 * 66; i += 256) ((float*)tile)[i] = 0.f;
    __syncthreads();                      // zero-init complete before any store

    int blk = blockIdx.x;                 // 128 blocks: n*16 + ytile
    int n   = blk >> 4;
    int y0  = (blk & 15) * 4;
    int p   = tid & 63, r = tid >> 6;     // pixel col, row-in-tile (0..3)

    // loader: threads 0..95 each load one float4 (row = t/16, col4 = t%16)
    int lrow = tid >> 4, lcol = (tid & 15) * 4;
    int gy   = y0 - 1 + lrow;
    bool lactive = tid < 96;
    bool lvalid  = lactive && (gy >= 0) && (gy < H_DIM);
    const float* lsrc = x + ((size_t)n * C_IN) * HW + gy * W_DIM + lcol;

    // prologue: load c = 0 into buf 0
    if (lactive) {
        float4 v = lvalid ? *(const float4*)lsrc : make_float4(0.f, 0.f, 0.f, 0.f);
        float* d = &tile[0][lrow * 66 + 1 + lcol];
        d[0] = v.x; d[1] = v.y; d[2] = v.z; d[3] = v.w;
    }
    __syncthreads();

    unsigned long long t01 = pack2(__ldg(b_tm + 0), __ldg(b_tm + 1));
    unsigned long long t23 = pack2(__ldg(b_tm + 2), __ldg(b_tm + 3));

    for (int c = 0; c < C_IN; ++c) {
        int b = c & 1;
        if (c + 1 < C_IN && lactive) {
            float4 v = lvalid ? __ldg((const float4*)(lsrc + (size_t)(c + 1) * HW))
                              : make_float4(0.f, 0.f, 0.f, 0.f);
            float* d = &tile[b ^ 1][lrow * 66 + 1 + lcol];
            d[0] = v.x; d[1] = v.y; d[2] = v.z; d[3] = v.w;
        }
        const float* base = &tile[b][(r + 1) * 66 + 1 + p];
#pragma unroll
        for (int k = 0; k < 9; ++k) {
            int dy = k / 3 - 1, dx = k % 3 - 1;
            float v = base[dy * 66 + dx];
            unsigned long long vv;
            asm("mov.b64 %0, {%1, %1};" : "=l"(vv) : "f"(v));
            asm("fma.rn.f32x2 %0, %1, %2, %0;" : "+l"(t01) : "l"(vv), "l"(ws01[c * 9 + k]));
            asm("fma.rn.f32x2 %0, %1, %2, %0;" : "+l"(t23) : "l"(vv), "l"(ws23[c * 9 + k]));
        }
        __syncthreads();
    }
    float t0, t1, t2, t3;
    asm("mov.b64 {%0, %1}, %2;" : "=f"(t0), "=f"(t1) : "l"(t01));
    asm("mov.b64 {%0, %1}, %2;" : "=f"(t2), "=f"(t3) : "l"(t23));
    g_T[((size_t)n * 64 + y0 + r) * 64 + p] = make_float4(t0, t1, t2, t3);
}

// ---------------------------------------------------------------------------
// Kernel 2: deformable conv, warp-MMA single-product fp16 GEMM.
// 256-thread CTAs (8 warps, warp tile 32Mx64N), 64-ck tiles (single tap),
// smem 94 KB -> 2 CTAs/SM (latency hiding across independent CTAs).
// A-store swizzle: group u offset is XOR 64 (SW128 is an XOR, not an add).
// ---------------------------------------------------------------------------
__global__ void __launch_bounds__(256, 2) k_deform(float* __restrict__ out) {
    extern __shared__ char smem[];
    const uint32_t sbase = smem_u32(smem);
    int tid  = threadIdx.x;
    int wid  = tid >> 5;
    int lane = tid & 31;
    int blk  = blockIdx.x;                 // n*64 + y
    int n    = blk >> 6;
    int y0   = blk & 63;

    // ---- bilinear params for 64 px x 9 taps ----
    ushort4* s_idx = (ushort4*)(smem + SM_IDX);
    float4*  s_wgt = (float4*)(smem + SM_WGT);
    for (int v = tid; v < 576; v += 256) {
        int p = v / 9, k = v - p * 9;
        float4 T = g_T[(size_t)blk * 64 + p];
        float dy = (float)(k / 3 - 1), dx = (float)(k % 3 - 1);
        float py = (float)y0 + T.x * dy + T.y * dx;
        float px = (float)p  + T.z * dy + T.w * dx;
        float y0f = floorf(py), x0f = floorf(px);
        float wy = py - y0f, wx = px - x0f;
        int iy0 = (int)y0f, ix0 = (int)x0f;
        int iy1 = iy0 + 1,  ix1 = ix0 + 1;
        bool vy0 = (iy0 >= 0) && (iy0 <= H_DIM - 1);
        bool vy1 = (iy1 >= 0) && (iy1 <= H_DIM - 1);
        bool vx0 = (ix0 >= 0) && (ix0 <= W_DIM - 1);
        bool vx1 = (ix1 >= 0) && (ix1 <= W_DIM - 1);
        int cy0 = min(H_DIM - 1, max(0, iy0)), cy1 = min(H_DIM - 1, max(0, iy1));
        int cx0 = min(W_DIM - 1, max(0, ix0)), cx1 = min(W_DIM - 1, max(0, ix1));
        float w00 = (vy0 && vx0) ? (1.f - wy) * (1.f - wx) : 0.f;
        float w01 = (vy0 && vx1) ? (1.f - wy) * wx         : 0.f;
        float w10 = (vy1 && vx0) ? wy * (1.f - wx)         : 0.f;
        float w11 = (vy1 && vx1) ? wy * wx                 : 0.f;
        s_idx[v] = make_ushort4((unsigned short)(cy0 * W_DIM + cx0),
                                (unsigned short)(cy0 * W_DIM + cx1),
                                (unsigned short)(cy1 * W_DIM + cx0),
                                (unsigned short)(cy1 * W_DIM + cx1));
        s_wgt[v] = make_float4(w00, w01, w10, w11);
    }
    __syncthreads();

    const __half* xtn = g_xt + (size_t)n * HW * C_IN;

    // builder mapping: px = tid>>2, groups g0 = tid&3 and g0+4 (8 ch each)
    const int bpx  = tid >> 2;
    const int bg0  = tid & 3;
    const int bpar = bpx * 9;
    const uint32_t abyte = (uint32_t)(bpx * 128 + bg0 * 16);
    const uint32_t asw0  = abyte ^ ((abyte >> 3) & 0x70);   // group g0

    // B cp.async: 8 x 16B per thread; base byte = tid*16, +4096 per step
    const uint32_t bbyte0 = (uint32_t)(tid * 16);
    const uint32_t bsw0   = bbyte0 ^ ((bbyte0 >> 3) & 0x70);
    const size_t   bg0f   = (size_t)(tid >> 3) * CK + (size_t)(tid & 7) * 8;

    // consumer mapping: warp tile 32(M) x 64(N); mw = wid&1, nw = wid>>1
    const int mw = wid & 1, nw = wid >> 1;
    const int arow = mw * 32 + (lane & 15);
    const uint32_t aswx = (uint32_t)((arow & 7) << 4);
    const uint32_t abase0 = (uint32_t)(arow * 128 + ((lane >> 4) << 4));
    const int nrow0 = nw * 64 + (lane >> 2);
    const uint32_t kpb = (uint32_t)((lane & 3) << 2);

    float acc[2][8][4];
#pragma unroll
    for (int m = 0; m < 2; m++)
#pragma unroll
        for (int f = 0; f < 8; f++)
#pragma unroll
            for (int r = 0; r < 4; r++) acc[m][f][r] = 0.f;

    // build one 64-ck tile (single tap k, 64 channels) into buffer `buf`
    auto build_tile = [&](int ckb, int buf) {
        uint32_t aBase = (uint32_t)(SM_A + buf * 8192);
        uint32_t bBase = (uint32_t)(SM_B + buf * 32768);
        // B: 8 async 16B copies
#pragma unroll
        for (int r = 0; r < 8; ++r)
            cpasync16(sbase + bBase + bsw0 + (uint32_t)(r * 4096),
                      (const void*)(g_wh + bg0f + (size_t)r * 32 * CK + ckb));
        // A: two 8-channel groups of one (p,k): 8 aligned 16B gathers
        const int kk = ckb >> 8;
        const int cb = ckb & 255;
        ushort4 id = s_idx[bpar + kk];
        float4  w  = s_wgt[bpar + kk];
#pragma unroll
        for (int u = 0; u < 2; ++u) {
            const __half* cbp = xtn + cb + bg0 * 8 + u * 32;
            uint4 A4 = __ldg((const uint4*)(cbp + (size_t)id.x * C_IN));
            uint4 B4 = __ldg((const uint4*)(cbp + (size_t)id.y * C_IN));
            uint4 C4 = __ldg((const uint4*)(cbp + (size_t)id.z * C_IN));
            uint4 D4 = __ldg((const uint4*)(cbp + (size_t)id.w * C_IN));
            uint32_t hr[4];
#pragma unroll
            for (int e = 0; e < 4; ++e) {
                float2 a = __half22float2(((const __half2*)&A4)[e]);
                float2 b = __half22float2(((const __half2*)&B4)[e]);
                float2 c = __half22float2(((const __half2*)&C4)[e]);
                float2 d = __half22float2(((const __half2*)&D4)[e]);
                float v0 = w.x * a.x + w.y * b.x + w.z * c.x + w.w * d.x;
                float v1 = w.x * a.y + w.y * b.y + w.z * c.y + w.w * d.y;
                __half2 hh = __floats2half2_rn(v0, v1);
                hr[e] = *(uint32_t*)&hh;
            }
            // group u: +64 bytes logical -> XOR 64 in swizzled space
            *(uint4*)(smem + aBase + (asw0 ^ (uint32_t)(u * 64)))
                = make_uint4(hr[0], hr[1], hr[2], hr[3]);
        }
        asm volatile("cp.async.commit_group;" ::: "memory");
    };

    // prologue
    build_tile(0, 0);
    asm volatile("cp.async.wait_group 0;" ::: "memory");
    __syncthreads();

    for (int t = 0; t < NT; ++t) {
        const int cur = t & 1;
        const uint32_t aB = sbase + (uint32_t)(SM_A + cur * 8192);
        const uint32_t bB = sbase + (uint32_t)(SM_B + cur * 32768);

        // ---- consume tile t: 4 k16 steps ----
#pragma unroll
        for (int s = 0; s < 4; ++s) {
            uint32_t ah0[4], ah1[4];
            uint32_t col = (uint32_t)(s * 32);
            uint32_t aoff0 = (abase0 + col) ^ aswx;
            ldmx4(ah0, aB + aoff0);
            ldmx4(ah1, aB + aoff0 + 2048);   // rows +16: same swizzle xor
#pragma unroll
            for (int f = 0; f < 8; ++f) {
                uint32_t bbyte = (uint32_t)((nrow0 + f * 8) * 128) + kpb + col;
                uint32_t swx = (bbyte >> 3) & 0x70;
                uint32_t b0, b1;
                lds32(b0, bB + (bbyte ^ swx));
                lds32(b1, bB + ((bbyte + 16) ^ swx));
                mma16816(acc[0][f], ah0, b0, b1);
                mma16816(acc[1][f], ah1, b0, b1);
            }
        }

        // ---- build tile t+1 (overlaps other CTA / laggard warps); sync ----
        if (t + 1 < NT) {
            build_tile((t + 1) * 64, cur ^ 1);
            asm volatile("cp.async.wait_group 0;" ::: "memory");
        }
        __syncthreads();
    }

    // ---- epilogue: stage to smem (o-major, px rows of 64, stride 68) ----
    float* so = (float*)(smem + SM_OUT);
#pragma unroll
    for (int m = 0; m < 2; ++m) {
        int rowg = mw * 32 + m * 16 + (lane >> 2);
#pragma unroll
        for (int f = 0; f < 8; ++f) {
            int o = nw * 64 + f * 8 + ((lane & 3) << 1);
            so[o * OSTR + rowg]           = acc[m][f][0];
            so[(o + 1) * OSTR + rowg]     = acc[m][f][1];
            so[o * OSTR + rowg + 8]       = acc[m][f][2];
            so[(o + 1) * OSTR + rowg + 8] = acc[m][f][3];
        }
    }
    __syncthreads();

    float* ob = out + (size_t)n * C_OUT * HW + y0 * 64;
    for (int q = tid; q < 256 * 16; q += 256) {
        int o = q >> 4, ch = q & 15;
        float4 v = *(float4*)(so + o * OSTR + ch * 4);
        *(float4*)(ob + (size_t)o * HW + ch * 4) = v;
    }
}

// ---------------------------------------------------------------------------
// Kernel 3: GroupNorm statistics. One block per (n, group): 8 ch x 4096 px.
// ---------------------------------------------------------------------------
__global__ void __launch_bounds__(256) k_gn_stats(const float* __restrict__ out) {
    int gidx = blockIdx.x;
    const float4* p = (const float4*)(out + (size_t)gidx * 8 * HW);
    int tid = threadIdx.x;
    float s = 0.f, s2 = 0.f;
    for (int i = tid; i < 8 * HW / 4; i += 256) {
        float4 v = p[i];
        s  += (v.x + v.y) + (v.z + v.w);
        s2  = fmaf(v.x, v.x, fmaf(v.y, v.y, fmaf(v.z, v.z, fmaf(v.w, v.w, s2))));
    }
    __shared__ float sh[2][8];
#pragma unroll
    for (int off = 16; off; off >>= 1) {
        s  += __shfl_down_sync(0xffffffffu, s, off);
        s2 += __shfl_down_sync(0xffffffffu, s2, off);
    }
    int warp = tid >> 5;
    if ((tid & 31) == 0) { sh[0][warp] = s; sh[1][warp] = s2; }
    __syncthreads();
    if (tid == 0) {
        float a = 0.f, bsum = 0.f;
#pragma unroll
        for (int i = 0; i < 8; i++) { a += sh[0][i]; bsum += sh[1][i]; }
        const float inv = 1.f / (8.f * HW);
        float mu  = a * inv;
        float var = bsum * inv - mu * mu;
        g_stats[gidx] = make_float2(mu, rsqrtf(var + EPS_GN));
    }
}

// ---------------------------------------------------------------------------
// Kernel 4: normalize + affine + ReLU, in place on d_out.
// ---------------------------------------------------------------------------
__global__ void __launch_bounds__(256) k_gn_norm(float* __restrict__ out,
                                                 const float* __restrict__ gamma,
                                                 const float* __restrict__ beta) {
    int f = blockIdx.x * 256 + threadIdx.x;
    int plane = f >> 10;
    int c = plane & 255;
    float2 st = g_stats[plane >> 3];
    float ga = __ldg(gamma + c) * st.y;
    float be = __ldg(beta + c) - st.x * ga;
    float4* p = (float4*)out + f;
    float4 v = *p;
    v.x = fmaxf(fmaf(v.x, ga, be), 0.f);
    v.y = fmaxf(fmaf(v.y, ga, be), 0.f);
    v.z = fmaxf(fmaf(v.z, ga, be), 0.f);
    v.w = fmaxf(fmaf(v.w, ga, be), 0.f);
    *p = v;
}

// ---------------------------------------------------------------------------
extern "C" void kernel_launch(void* const* d_in, const int* in_sizes, int n_in,
                              void* d_out, int out_size) {
    (void)in_sizes; (void)n_in; (void)out_size;
    const float* x     = (const float*)d_in[0];
    const float* w_tm  = (const float*)d_in[1];
    const float* b_tm  = (const float*)d_in[2];
    const float* w_dcn = (const float*)d_in[3];
    const float* gamma = (const float*)d_in[4];
    const float* beta  = (const float*)d_in[5];
    float* out = (float*)d_out;

    cudaFuncSetAttribute(k_deform, cudaFuncAttributeMaxDynamicSharedMemorySize, SM_TOTAL);

    k_prep_w<<<(C_OUT * CK + 255) / 256, 256>>>(w_dcn);
    {
        dim3 g(HW / 32, C_IN / 32, N_IMG);
        dim3 b(32, 8, 1);
        k_prep_x<<<g, b>>>(x);
    }
    k_offsets<<<N_IMG * 16, 256>>>(x, w_tm, b_tm);
    // k_deform stays 4th launch -> remains in ncu's profiled slot
    k_deform<<<N_IMG * H_DIM, 256, SM_TOTAL>>>(out);
    k_gn_stats<<<N_IMG * GROUPS, 256>>>(out);
    k_gn_norm<<<(N_IMG * C_OUT * HW / 4) / 256, 256>>>(out, gamma, beta);
}

// round 17
// speedup vs baseline: 1.7551x; 1.7551x over previous
#include <cuda_runtime.h>
#include <cuda_fp16.h>
#include <cstdint>

#define N_IMG 8
#define C_IN  256
#define C_OUT 256
#define H_DIM 64
#define W_DIM 64
#define HW    4096
#define GROUPS 32
#define EPS_GN 1e-5f
#define CK    (C_IN * 9)   // 2304
#define NMT   18           // macro K-tiles (128 ck' each, single tap k per macro)

// ---- dynamic smem layout for k_deform (bytes) ----
#define SM_IDX   0                    // ushort4[576] = 4608
#define SM_WGT   4608                 // float4[576]  = 9216 -> 13824, pad 14336
#define SM_A     14336                // 2 bufs x 2 subtiles x 8192 = 32768
#define SM_B     47104                // 2 bufs x 2 subtiles x 32768 = 131072
#define SM_TOTAL 178176
#define SM_OUT   SM_A                 // epilogue reuses A+B region (needs 69632)
#define OSTR     68                   // f32 stride for out staging rows

static __device__ __forceinline__ uint32_t smem_u32(const void* p) {
    uint32_t a;
    asm("{ .reg .u64 t; cvta.to.shared.u64 t, %1; cvt.u32.u64 %0, t; }" : "=r"(a) : "l"(p));
    return a;
}
static __device__ __forceinline__ void lds32(uint32_t& d, uint32_t a) {
    asm volatile("ld.shared.b32 %0, [%1];" : "=r"(d) : "r"(a));
}
static __device__ __forceinline__ void ldmx4(uint32_t* r, uint32_t a) {
    asm volatile("ldmatrix.sync.aligned.m8n8.x4.shared.b16 {%0,%1,%2,%3}, [%4];"
                 : "=r"(r[0]), "=r"(r[1]), "=r"(r[2]), "=r"(r[3]) : "r"(a));
}
static __device__ __forceinline__ void mma16816(float* c, const uint32_t* a,
                                                uint32_t b0, uint32_t b1) {
    asm volatile("mma.sync.aligned.m16n8k16.row.col.f32.f16.f16.f32 "
                 "{%0,%1,%2,%3}, {%4,%5,%6,%7}, {%8,%9}, {%0,%1,%2,%3};"
                 : "+f"(c[0]), "+f"(c[1]), "+f"(c[2]), "+f"(c[3])
                 : "r"(a[0]), "r"(a[1]), "r"(a[2]), "r"(a[3]), "r"(b0), "r"(b1));
}
static __device__ __forceinline__ void cpasync16(uint32_t saddr, const void* g) {
    asm volatile("cp.async.cg.shared.global [%0], [%1], 16;" :: "r"(saddr), "l"(g) : "memory");
}
__device__ __forceinline__ unsigned long long pack2(float lo, float hi) {
    unsigned long long r;
    asm("mov.b64 %0, {%1, %2};" : "=l"(r) : "f"(lo), "f"(hi));
    return r;
}

// Scratch (static device globals; no runtime allocation)
__device__ float4 g_T[N_IMG * HW];                    // per-pixel 2x2 transform
__device__ __align__(16) __half g_wh[C_OUT * CK];     // weight fp16 [o][k*256+c]
__device__ __align__(16) __half g_xt[N_IMG * HW * C_IN]; // x fp16, [n][pix][c]
__device__ float2 g_stats[N_IMG * GROUPS];            // (mu, rsigma)

// ---------------------------------------------------------------------------
// Kernel 0a: w_dcn [o][c][k] -> fp16 g_wh [o][k*256+c]; also zeroes g_T
// (k_offsets accumulates into g_T atomically).
// ---------------------------------------------------------------------------
__global__ void k_prep_w(const float* __restrict__ w) {
    int i = blockIdx.x * 256 + threadIdx.x;          // i = (o*256+c)*9 + k
    if (i < N_IMG * HW) g_T[i] = make_float4(0.f, 0.f, 0.f, 0.f);
    if (i >= C_OUT * CK) return;
    int k = i % 9;
    int oc = i / 9;
    int o = oc >> 8, c = oc & 255;
    g_wh[(size_t)o * CK + k * 256 + c] = __float2half_rn(w[i]);
}

// ---------------------------------------------------------------------------
// Kernel 0b: transpose x [n][c][pix] fp32 -> g_xt [n][pix][c] fp16 (tiled)
// ---------------------------------------------------------------------------
__global__ void __launch_bounds__(256) k_prep_x(const float* __restrict__ x) {
    __shared__ __half tile[32][33];
    int pt = blockIdx.x * 32;            // pixel tile
    int ct = blockIdx.y * 32;            // channel tile
    int n  = blockIdx.z;
    int tx = threadIdx.x, ty = threadIdx.y;   // (32, 8)
    const float* xb = x + ((size_t)n * C_IN + ct) * HW + pt;
#pragma unroll
    for (int i = ty; i < 32; i += 8)
        tile[i][tx] = __float2half_rn(xb[(size_t)i * HW + tx]);
    __syncthreads();
    __half* ob = g_xt + ((size_t)n * HW + pt) * C_IN + ct;
#pragma unroll
    for (int i = ty; i < 32; i += 8)
        ob[(size_t)i * C_IN + tx] = tile[tx][i];
}

// ---------------------------------------------------------------------------
// Kernel 1: tm = conv3x3(x, w_tm) + b_tm, channel-chunked.
// Block = (n, 4-row ytile, chunk of 64 channels). Smem row-tiling with
// double buffer; 64 iterations; partial T accumulated and atomicAdd'ed to
// g_T (zeroed in k_prep_w). Bias added by chunk 0 only. 512 CTAs -> 3.5
// waves + high occupancy hides per-channel load latency.
// ---------------------------------------------------------------------------
__global__ void __launch_bounds__(256) k_offsets(const float* __restrict__ x,
                                                 const float* __restrict__ w_tm,
                                                 const float* __restrict__ b_tm) {
    __shared__ unsigned long long ws01[576];
    __shared__ unsigned long long ws23[576];
    __shared__ float tile[2][6 * 66];
    int tid = threadIdx.x;
    int blk = blockIdx.x;                 // ((n*16 + ytile) << 2) | chunk
    int chunk = blk & 3;
    int nyt = blk >> 2;
    int n   = nyt >> 4;
    int y0  = (nyt & 15) * 4;
    int ch0 = chunk * 64;

    for (int i = tid; i < 576; i += 256) {
        int ck = ch0 * 9 + i;
        ws01[i] = pack2(w_tm[ck],          w_tm[CK + ck]);
        ws23[i] = pack2(w_tm[2 * CK + ck], w_tm[3 * CK + ck]);
    }
    for (int i = tid; i < 2 * 6 * 66; i += 256) ((float*)tile)[i] = 0.f;
    __syncthreads();                      // zero-init complete before stores

    int p = tid & 63, r = tid >> 6;       // pixel col, row-in-tile (0..3)
    int lrow = tid >> 4, lcol = (tid & 15) * 4;
    int gy   = y0 - 1 + lrow;
    bool lactive = tid < 96;
    bool lvalid  = lactive && (gy >= 0) && (gy < H_DIM);
    const float* lsrc = x + ((size_t)n * C_IN + ch0) * HW + gy * W_DIM + lcol;

    if (lactive) {
        float4 v = lvalid ? *(const float4*)lsrc : make_float4(0.f, 0.f, 0.f, 0.f);
        float* d = &tile[0][lrow * 66 + 1 + lcol];
        d[0] = v.x; d[1] = v.y; d[2] = v.z; d[3] = v.w;
    }
    __syncthreads();

    unsigned long long t01 = 0ULL, t23 = 0ULL;   // two packed 0.0f
    if (chunk == 0) {
        t01 = pack2(__ldg(b_tm + 0), __ldg(b_tm + 1));
        t23 = pack2(__ldg(b_tm + 2), __ldg(b_tm + 3));
    }

    for (int c = 0; c < 64; ++c) {
        int b = c & 1;
        if (c + 1 < 64 && lactive) {
            float4 v = lvalid ? __ldg((const float4*)(lsrc + (size_t)(c + 1) * HW))
                              : make_float4(0.f, 0.f, 0.f, 0.f);
            float* d = &tile[b ^ 1][lrow * 66 + 1 + lcol];
            d[0] = v.x; d[1] = v.y; d[2] = v.z; d[3] = v.w;
        }
        const float* base = &tile[b][(r + 1) * 66 + 1 + p];
#pragma unroll
        for (int k = 0; k < 9; ++k) {
            int dy = k / 3 - 1, dx = k % 3 - 1;
            float v = base[dy * 66 + dx];
            unsigned long long vv;
            asm("mov.b64 %0, {%1, %1};" : "=l"(vv) : "f"(v));
            asm("fma.rn.f32x2 %0, %1, %2, %0;" : "+l"(t01) : "l"(vv), "l"(ws01[c * 9 + k]));
            asm("fma.rn.f32x2 %0, %1, %2, %0;" : "+l"(t23) : "l"(vv), "l"(ws23[c * 9 + k]));
        }
        __syncthreads();
    }
    float t0, t1, t2, t3;
    asm("mov.b64 {%0, %1}, %2;" : "=f"(t0), "=f"(t1) : "l"(t01));
    asm("mov.b64 {%0, %1}, %2;" : "=f"(t2), "=f"(t3) : "l"(t23));
    float* gp = (float*)&g_T[((size_t)n * 64 + y0 + r) * 64 + p];
    atomicAdd(gp + 0, t0);
    atomicAdd(gp + 1, t1);
    atomicAdd(gp + 2, t2);
    atomicAdd(gp + 3, t3);
}

// ---------------------------------------------------------------------------
// Kernel 2: deformable conv (exact R14-proven version, 186 us).
// K-ordering ck' = k*256 + c: each macro-tile (128 ck') = ONE tap k, 128 ch.
// Builder: 4 aligned LDG.128 per 8 values; double-buffered; B via cp.async;
// consume-then-build; 512 threads, warp tile 32Mx32N; spill-free.
// ---------------------------------------------------------------------------
__global__ void __launch_bounds__(512, 1) k_deform(float* __restrict__ out) {
    extern __shared__ char smem[];
    const uint32_t sbase = smem_u32(smem);
    int tid  = threadIdx.x;
    int wid  = tid >> 5;
    int lane = tid & 31;
    int blk  = blockIdx.x;                 // n*64 + y
    int n    = blk >> 6;
    int y0   = blk & 63;

    // ---- bilinear params for 64 px x 9 taps ----
    ushort4* s_idx = (ushort4*)(smem + SM_IDX);
    float4*  s_wgt = (float4*)(smem + SM_WGT);
    for (int v = tid; v < 576; v += 512) {
        int p = v / 9, k = v - p * 9;
        float4 T = g_T[(size_t)blk * 64 + p];
        float dy = (float)(k / 3 - 1), dx = (float)(k % 3 - 1);
        float py = (float)y0 + T.x * dy + T.y * dx;
        float px = (float)p  + T.z * dy + T.w * dx;
        float y0f = floorf(py), x0f = floorf(px);
        float wy = py - y0f, wx = px - x0f;
        int iy0 = (int)y0f, ix0 = (int)x0f;
        int iy1 = iy0 + 1,  ix1 = ix0 + 1;
        bool vy0 = (iy0 >= 0) && (iy0 <= H_DIM - 1);
        bool vy1 = (iy1 >= 0) && (iy1 <= H_DIM - 1);
        bool vx0 = (ix0 >= 0) && (ix0 <= W_DIM - 1);
        bool vx1 = (ix1 >= 0) && (ix1 <= W_DIM - 1);
        int cy0 = min(H_DIM - 1, max(0, iy0)), cy1 = min(H_DIM - 1, max(0, iy1));
        int cx0 = min(W_DIM - 1, max(0, ix0)), cx1 = min(W_DIM - 1, max(0, ix1));
        float w00 = (vy0 && vx0) ? (1.f - wy) * (1.f - wx) : 0.f;
        float w01 = (vy0 && vx1) ? (1.f - wy) * wx         : 0.f;
        float w10 = (vy1 && vx0) ? wy * (1.f - wx)         : 0.f;
        float w11 = (vy1 && vx1) ? wy * wx                 : 0.f;
        s_idx[v] = make_ushort4((unsigned short)(cy0 * W_DIM + cx0),
                                (unsigned short)(cy0 * W_DIM + cx1),
                                (unsigned short)(cy1 * W_DIM + cx0),
                                (unsigned short)(cy1 * W_DIM + cx1));
        s_wgt[v] = make_float4(w00, w01, w10, w11);
    }
    __syncthreads();

    const __half* xtn = g_xt + (size_t)n * HW * C_IN;

    // builder mapping: px = tid>>3 (4 px per warp), ch-group (8 ch) = tid&7
    const int bpx  = tid >> 3;
    const int bckg = tid & 7;
    const int bpar = bpx * 9;
    const int bck0 = bckg * 8;
    const uint32_t abyte = (uint32_t)(bpx * 128 + bckg * 16);
    const uint32_t asw   = abyte ^ ((abyte >> 3) & 0x70);

    // B cp.async mapping: 4 x 16B per thread per subtile
    uint32_t bsw[4];
    size_t   bgofs[4];
#pragma unroll
    for (int r = 0; r < 4; ++r) {
        int q = tid + (r << 9);            // 0..2047
        int o = q >> 3, j = q & 7;
        uint32_t byte = (uint32_t)(o * 128 + j * 16);
        bsw[r]   = byte ^ ((byte >> 3) & 0x70);
        bgofs[r] = (size_t)o * CK + j * 8;
    }

    // consumer mapping: warp tile 32(M) x 32(N); mw = wid&1, nw = wid>>1
    const int mw = wid & 1, nw = wid >> 1;
    const int arow = mw * 32 + (lane & 15);
    const uint32_t aswx = (uint32_t)((arow & 7) << 4);
    const uint32_t abase0 = (uint32_t)(arow * 128 + ((lane >> 4) << 4));
    const int nrow0 = nw * 32 + (lane >> 2);
    const uint32_t kpb = (uint32_t)((lane & 3) << 2);

    float acc[2][4][4];
#pragma unroll
    for (int m = 0; m < 2; m++)
#pragma unroll
        for (int f = 0; f < 4; f++)
#pragma unroll
            for (int r = 0; r < 4; r++) acc[m][f][r] = 0.f;

    // build one macro-tile (single tap k, 128 channels; 2 subtiles) into `buf`
    auto build_macro = [&](int ckb, int buf) {
        uint32_t aBase = (uint32_t)(SM_A + buf * 16384);
        uint32_t bBase = (uint32_t)(SM_B + buf * 65536);
        const int kk = ckb >> 8;                 // tap for the whole macro-tile
        ushort4 id = s_idx[bpar + kk];
        float4  w  = s_wgt[bpar + kk];
#pragma unroll
        for (int u = 0; u < 2; ++u) {
            // B: async copy, no registers
#pragma unroll
            for (int r = 0; r < 4; ++r)
                cpasync16(sbase + bBase + (uint32_t)(u * 32768) + bsw[r],
                          (const void*)(g_wh + bgofs[r] + ckb + u * 64));
            // A: 8 consecutive channels of one (p,k): 4 aligned 16B gathers
            const __half* cb = xtn + (ckb & 255) + u * 64 + bck0;
            uint4 A4 = __ldg((const uint4*)(cb + (size_t)id.x * C_IN));
            uint4 B4 = __ldg((const uint4*)(cb + (size_t)id.y * C_IN));
            uint4 C4 = __ldg((const uint4*)(cb + (size_t)id.z * C_IN));
            uint4 D4 = __ldg((const uint4*)(cb + (size_t)id.w * C_IN));
            uint32_t hr[4];
#pragma unroll
            for (int e = 0; e < 4; ++e) {
                float2 a = __half22float2(((const __half2*)&A4)[e]);
                float2 b = __half22float2(((const __half2*)&B4)[e]);
                float2 c = __half22float2(((const __half2*)&C4)[e]);
                float2 d = __half22float2(((const __half2*)&D4)[e]);
                float v0 = w.x * a.x + w.y * b.x + w.z * c.x + w.w * d.x;
                float v1 = w.x * a.y + w.y * b.y + w.z * c.y + w.w * d.y;
                __half2 hh = __floats2half2_rn(v0, v1);
                hr[e] = *(uint32_t*)&hh;
            }
            *(uint4*)(smem + aBase + (uint32_t)(u * 8192) + asw)
                = make_uint4(hr[0], hr[1], hr[2], hr[3]);
        }
        asm volatile("cp.async.commit_group;" ::: "memory");
    };

    // prologue: build macro-tile 0 into buffer 0
    build_macro(0, 0);
    asm volatile("cp.async.wait_group 0;" ::: "memory");
    __syncthreads();

    for (int t = 0; t < NMT; ++t) {
        const int cur = t & 1;

        // ---- consume macro-tile t: 2 subtiles x 4 k16 steps ----
#pragma unroll
        for (int u = 0; u < 2; ++u) {
            const uint32_t aB = sbase + (uint32_t)(SM_A + cur * 16384 + u * 8192);
            const uint32_t bB = sbase + (uint32_t)(SM_B + cur * 65536 + u * 32768);
#pragma unroll
            for (int s = 0; s < 4; ++s) {
                uint32_t ah0[4], ah1[4];
                uint32_t col = (uint32_t)(s * 32);
                uint32_t aoff0 = (abase0 + col) ^ aswx;
                ldmx4(ah0, aB + aoff0);
                ldmx4(ah1, aB + aoff0 + 2048);   // rows +16: same swizzle xor
#pragma unroll
                for (int f = 0; f < 4; ++f) {
                    uint32_t bbyte = (uint32_t)((nrow0 + f * 8) * 128) + kpb + col;
                    uint32_t swx = (bbyte >> 3) & 0x70;
                    uint32_t b0, b1;
                    lds32(b0, bB + (bbyte ^ swx));
                    lds32(b1, bB + ((bbyte + 16) ^ swx));
                    mma16816(acc[0][f], ah0, b0, b1);
                    mma16816(acc[1][f], ah1, b0, b1);
                }
            }
        }

        // ---- build macro-tile t+1 (overlaps laggards' MMAs); drain; sync ----
        if (t + 1 < NMT) {
            build_macro((t + 1) * 128, cur ^ 1);
            asm volatile("cp.async.wait_group 0;" ::: "memory");
        }
        __syncthreads();
    }

    // ---- epilogue: stage to smem (o-major, px rows of 64, stride 68) ----
    float* so = (float*)(smem + SM_OUT);
#pragma unroll
    for (int m = 0; m < 2; ++m) {
        int rowg = mw * 32 + m * 16 + (lane >> 2);
#pragma unroll
        for (int f = 0; f < 4; ++f) {
            int o = nw * 32 + f * 8 + ((lane & 3) << 1);
            so[o * OSTR + rowg]           = acc[m][f][0];
            so[(o + 1) * OSTR + rowg]     = acc[m][f][1];
            so[o * OSTR + rowg + 8]       = acc[m][f][2];
            so[(o + 1) * OSTR + rowg + 8] = acc[m][f][3];
        }
    }
    __syncthreads();

    float* ob = out + (size_t)n * C_OUT * HW + y0 * 64;
    for (int q = tid; q < 256 * 16; q += 512) {
        int o = q >> 4, ch = q & 15;
        float4 v = *(float4*)(so + o * OSTR + ch * 4);
        *(float4*)(ob + (size_t)o * HW + ch * 4) = v;
    }
}

// ---------------------------------------------------------------------------
// Kernel 3: GroupNorm statistics. One block per (n, group): 8 ch x 4096 px.
// ---------------------------------------------------------------------------
__global__ void __launch_bounds__(256) k_gn_stats(const float* __restrict__ out) {
    int gidx = blockIdx.x;
    const float4* p = (const float4*)(out + (size_t)gidx * 8 * HW);
    int tid = threadIdx.x;
    float s = 0.f, s2 = 0.f;
    for (int i = tid; i < 8 * HW / 4; i += 256) {
        float4 v = p[i];
        s  += (v.x + v.y) + (v.z + v.w);
        s2  = fmaf(v.x, v.x, fmaf(v.y, v.y, fmaf(v.z, v.z, fmaf(v.w, v.w, s2))));
    }
    __shared__ float sh[2][8];
#pragma unroll
    for (int off = 16; off; off >>= 1) {
        s  += __shfl_down_sync(0xffffffffu, s, off);
        s2 += __shfl_down_sync(0xffffffffu, s2, off);
    }
    int warp = tid >> 5;
    if ((tid & 31) == 0) { sh[0][warp] = s; sh[1][warp] = s2; }
    __syncthreads();
    if (tid == 0) {
        float a = 0.f, bsum = 0.f;
#pragma unroll
        for (int i = 0; i < 8; i++) { a += sh[0][i]; bsum += sh[1][i]; }
        const float inv = 1.f / (8.f * HW);
        float mu  = a * inv;
        float var = bsum * inv - mu * mu;
        g_stats[gidx] = make_float2(mu, rsqrtf(var + EPS_GN));
    }
}

// ---------------------------------------------------------------------------
// Kernel 4: normalize + affine + ReLU, in place on d_out.
// ---------------------------------------------------------------------------
__global__ void __launch_bounds__(256) k_gn_norm(float* __restrict__ out,
                                                 const float* __restrict__ gamma,
                                                 const float* __restrict__ beta) {
    int f = blockIdx.x * 256 + threadIdx.x;
    int plane = f >> 10;
    int c = plane & 255;
    float2 st = g_stats[plane >> 3];
    float ga = __ldg(gamma + c) * st.y;
    float be = __ldg(beta + c) - st.x * ga;
    float4* p = (float4*)out + f;
    float4 v = *p;
    v.x = fmaxf(fmaf(v.x, ga, be), 0.f);
    v.y = fmaxf(fmaf(v.y, ga, be), 0.f);
    v.z = fmaxf(fmaf(v.z, ga, be), 0.f);
    v.w = fmaxf(fmaf(v.w, ga, be), 0.f);
    *p = v;
}

// ---------------------------------------------------------------------------
extern "C" void kernel_launch(void* const* d_in, const int* in_sizes, int n_in,
                              void* d_out, int out_size) {
    (void)in_sizes; (void)n_in; (void)out_size;
    const float* x     = (const float*)d_in[0];
    const float* w_tm  = (const float*)d_in[1];
    const float* b_tm  = (const float*)d_in[2];
    const float* w_dcn = (const float*)d_in[3];
    const float* gamma = (const float*)d_in[4];
    const float* beta  = (const float*)d_in[5];
    float* out = (float*)d_out;

    cudaFuncSetAttribute(k_deform, cudaFuncAttributeMaxDynamicSharedMemorySize, SM_TOTAL);

    k_prep_w<<<(C_OUT * CK + 255) / 256, 256>>>(w_dcn);
    {
        dim3 g(HW / 32, C_IN / 32, N_IMG);
        dim3 b(32, 8, 1);
        k_prep_x<<<g, b>>>(x);
    }
    k_offsets<<<N_IMG * 16 * 4, 256>>>(x, w_tm, b_tm);
    // k_deform stays 4th launch -> remains in ncu's profiled slot
    k_deform<<<N_IMG * H_DIM, 512, SM_TOTAL>>>(out);
    k_gn_stats<<<N_IMG * GROUPS, 256>>>(out);
    k_gn_norm<<<(N_IMG * C_OUT * HW / 4) / 256, 256>>>(out, gamma, beta);
}